// round 10
// baseline (speedup 1.0000x reference)
#include <cuda_runtime.h>

// GeneralMechanismODE — single-touch stream (96 B in, 32 B out per row).
// R10 hybrid of the two best-measured halves:
//   READ  path (from R9, best ncu window 24.4us): one ld.global.v8.f32 per
//          y row — fewer memory instructions / L1tex wavefronts.
//   WRITE path (from R7, best wall 28.7us): 2x __stwt float4 — the .wt.v8
//          store correlated with the R9 wall regression.
//   Rates: __ldcs float4 (unchanged since R3; R8 proved default policy hurts).
// Block 128 (churn optimum, R5/R6), straight-line body, no loop hazards.

__global__ __launch_bounds__(128) void ode_kernel10(
    const float* __restrict__ y,     // B x 8
    const float4* __restrict__ kf,   // B float4
    const float4* __restrict__ kr,   // B float4
    float4* __restrict__ out,        // 2*B float4
    int B)
{
    int b = blockIdx.x * blockDim.x + threadIdx.x;
    if (b >= B) return;

    // One 256-bit load for the whole y row (32-byte aligned).
    float y0, y1, y2, y3, y4, y5, y6, y7;
    asm volatile(
        "ld.global.v8.f32 {%0, %1, %2, %3, %4, %5, %6, %7}, [%8];"
        : "=f"(y0), "=f"(y1), "=f"(y2), "=f"(y3),
          "=f"(y4), "=f"(y5), "=f"(y6), "=f"(y7)
        : "l"(y + (size_t)b * 8));

    float4 f = __ldcs(&kf[b]);
    float4 r = __ldcs(&kr[b]);

    float v0 = f.x * y0 * y4 - r.x * y1;        // kf0*E*A  - kr0*EA
    float v1 = f.y * y1 * y5 - r.y * y3;        // kf1*EA*B - kr1*EAB
    float v2 = f.z * y3      - r.z * y2 * y6;   // kf2*EAB  - kr2*EQ*P
    float v3 = f.w * y2      - r.w * y0 * y7;   // kf3*EQ   - kr3*E*Q

    float4 olo, ohi;
    olo.x = v3 - v0;   // dE
    olo.y = v0 - v1;   // dEA
    olo.z = v2 - v3;   // dEQ
    olo.w = v1 - v2;   // dEAB
    ohi.x = -v0;       // dA
    ohi.y = -v1;       // dB
    ohi.z = v2;        // dP
    ohi.w = v3;        // dQ

    __stwt(&out[2 * b + 0], olo);
    __stwt(&out[2 * b + 1], ohi);
}

extern "C" void kernel_launch(void* const* d_in, const int* in_sizes, int n_in,
                              void* d_out, int out_size)
{
    // metadata order: t (1), y (B*8), forward_rates (B*4), reverse_rates (B*4)
    const float*  y  = (const float*)d_in[1];
    const float4* kf = (const float4*)d_in[2];
    const float4* kr = (const float4*)d_in[3];
    float4* out = (float4*)d_out;

    int B = in_sizes[1] / 8;
    int threads = 128;
    int blocks = (B + threads - 1) / threads;
    ode_kernel10<<<blocks, threads>>>(y, kf, kr, out, B);
}

// round 11
// speedup vs baseline: 1.0685x; 1.0685x over previous
#include <cuda_runtime.h>

// GeneralMechanismODE — single-touch stream (96 B in, 32 B out per row).
// R11: byte-identical resubmission of the R7 winner (28.7us) as a
// reproducibility re-bench. History shows ncu-window time is stable
// (24.4-25.6us across all good configs) while wall scatters +/-1.5us;
// R7 is the only config ever under 29us wall and has a near-best window.
// Config: block 128 (churn optimum), 1 row/thread, no loop-carried hazards,
// 4 front-batched LDG.128 with .cs (evict-first, zero reuse), .wt stores
// (no L2 dirty allocation / writeback turnaround between graph replays).

__global__ __launch_bounds__(128) void ode_kernel11(
    const float4* __restrict__ y,    // 2*B float4
    const float4* __restrict__ kf,   // B float4
    const float4* __restrict__ kr,   // B float4
    float4* __restrict__ out,        // 2*B float4
    int B)
{
    int b = blockIdx.x * blockDim.x + threadIdx.x;
    if (b >= B) return;

    // 4 independent 128-bit streaming loads, front-batched.
    float4 ylo = __ldcs(&y[2 * b + 0]);   // y0..y3
    float4 yhi = __ldcs(&y[2 * b + 1]);   // y4..y7
    float4 f   = __ldcs(&kf[b]);
    float4 r   = __ldcs(&kr[b]);

    float v0 = f.x * ylo.x * yhi.x - r.x * ylo.y;          // kf0*E*A  - kr0*EA
    float v1 = f.y * ylo.y * yhi.y - r.y * ylo.w;          // kf1*EA*B - kr1*EAB
    float v2 = f.z * ylo.w         - r.z * ylo.z * yhi.z;  // kf2*EAB  - kr2*EQ*P
    float v3 = f.w * ylo.z         - r.w * ylo.x * yhi.w;  // kf3*EQ   - kr3*E*Q

    float4 olo, ohi;
    olo.x = v3 - v0;   // dE
    olo.y = v0 - v1;   // dEA
    olo.z = v2 - v3;   // dEQ
    olo.w = v1 - v2;   // dEAB
    ohi.x = -v0;       // dA
    ohi.y = -v1;       // dB
    ohi.z = v2;        // dP
    ohi.w = v3;        // dQ

    __stwt(&out[2 * b + 0], olo);
    __stwt(&out[2 * b + 1], ohi);
}

extern "C" void kernel_launch(void* const* d_in, const int* in_sizes, int n_in,
                              void* d_out, int out_size)
{
    // metadata order: t (1), y (B*8), forward_rates (B*4), reverse_rates (B*4)
    const float4* y  = (const float4*)d_in[1];
    const float4* kf = (const float4*)d_in[2];
    const float4* kr = (const float4*)d_in[3];
    float4* out = (float4*)d_out;

    int B = in_sizes[1] / 8;
    int threads = 128;
    int blocks = (B + threads - 1) / threads;
    ode_kernel11<<<blocks, threads>>>(y, kf, kr, out, B);
}

// round 12
// speedup vs baseline: 1.0790x; 1.0099x over previous
#include <cuda_runtime.h>

// GeneralMechanismODE — single-touch stream (96 B in, 32 B out per row).
// R12: R7 winning config (block 128, 4x LDG.128 evict-first, 2x STG.128
// write-through — the only config with sub-29.5 walls: 28.7 / 29.4) plus
// L2::256B prefetch hints on the streaming loads. Streams are dense, so the
// prefetched neighborhood is guaranteed-useful: converts demand misses into
// L2 hits / longer DRAM row bursts at zero extra traffic. v8 loads dropped
// permanently: best windows but consistently worst walls (R9/R10).

__device__ __forceinline__ float4 ldcs_pf256(const float4* p) {
    float4 v;
    asm volatile("ld.global.cs.L2::256B.v4.f32 {%0, %1, %2, %3}, [%4];"
                 : "=f"(v.x), "=f"(v.y), "=f"(v.z), "=f"(v.w)
                 : "l"(p));
    return v;
}

__global__ __launch_bounds__(128) void ode_kernel12(
    const float4* __restrict__ y,    // 2*B float4
    const float4* __restrict__ kf,   // B float4
    const float4* __restrict__ kr,   // B float4
    float4* __restrict__ out,        // 2*B float4
    int B)
{
    int b = blockIdx.x * blockDim.x + threadIdx.x;
    if (b >= B) return;

    // 4 independent 128-bit streaming loads with L2 256B prefetch, front-batched.
    float4 ylo = ldcs_pf256(&y[2 * b + 0]);   // y0..y3
    float4 yhi = ldcs_pf256(&y[2 * b + 1]);   // y4..y7
    float4 f   = ldcs_pf256(&kf[b]);
    float4 r   = ldcs_pf256(&kr[b]);

    float v0 = f.x * ylo.x * yhi.x - r.x * ylo.y;          // kf0*E*A  - kr0*EA
    float v1 = f.y * ylo.y * yhi.y - r.y * ylo.w;          // kf1*EA*B - kr1*EAB
    float v2 = f.z * ylo.w         - r.z * ylo.z * yhi.z;  // kf2*EAB  - kr2*EQ*P
    float v3 = f.w * ylo.z         - r.w * ylo.x * yhi.w;  // kf3*EQ   - kr3*E*Q

    float4 olo, ohi;
    olo.x = v3 - v0;   // dE
    olo.y = v0 - v1;   // dEA
    olo.z = v2 - v3;   // dEQ
    olo.w = v1 - v2;   // dEAB
    ohi.x = -v0;       // dA
    ohi.y = -v1;       // dB
    ohi.z = v2;        // dP
    ohi.w = v3;        // dQ

    __stwt(&out[2 * b + 0], olo);
    __stwt(&out[2 * b + 1], ohi);
}

extern "C" void kernel_launch(void* const* d_in, const int* in_sizes, int n_in,
                              void* d_out, int out_size)
{
    // metadata order: t (1), y (B*8), forward_rates (B*4), reverse_rates (B*4)
    const float4* y  = (const float4*)d_in[1];
    const float4* kf = (const float4*)d_in[2];
    const float4* kr = (const float4*)d_in[3];
    float4* out = (float4*)d_out;

    int B = in_sizes[1] / 8;
    int threads = 128;
    int blocks = (B + threads - 1) / threads;
    ode_kernel12<<<blocks, threads>>>(y, kf, kr, out, B);
}